// round 3
// baseline (speedup 1.0000x reference)
#include <cuda_runtime.h>
#include <cstdint>

// GateRecurrent2dnoind: H[:,:,h,w] = B*X + G1*H[h-1,w-1] + G2*H[h,w-1] + G3*H[h+1,w-1]
// (8, 96, 128, 128) -> 768 independent (128 x 128) planes, serial scan over W.
//
// Round-3 design: R2 was latency-bound (DRAM 53.5%, occ 11.4%, issue 12.4%) on
// a 128-step serial chain paying LDS+BAR every step. This version computes the
// recurrence in ONE warp per plane with 4 contiguous rows per lane:
//   - carry column in registers (4 floats/lane)
//   - vertical taps: interior = registers, boundary = 2 shfls/step, NO barriers
//   - warps 1-3 only cooperate on the (unchanged, proven) cp.async chunk loader
//     and coalesced store; 2 block barriers per chunk (16/plane vs 128).
// Staging layout identical to R2: 16-col chunks, stride-20 rows, double buffer.

#define H_DIM   128
#define W_DIM   128
#define CW      16                  // staged chunk width (columns)
#define NCH     (W_DIM / CW)        // 8 chunks
#define RSTRIDE 20                  // padded row stride (floats)
#define TILE_F  (H_DIM * RSTRIDE)   // 2560 floats per array tile
#define NARR    5

__device__ __forceinline__ void cp_async16(uint32_t dst, const float* src) {
    asm volatile("cp.async.cg.shared.global [%0], [%1], 16;\n" :: "r"(dst), "l"(src));
}
__device__ __forceinline__ void cp_commit() {
    asm volatile("cp.async.commit_group;\n" ::: "memory");
}
template <int N>
__device__ __forceinline__ void cp_wait() {
    asm volatile("cp.async.wait_group %0;\n" :: "n"(N) : "memory");
}

__global__ void __launch_bounds__(H_DIM, 2)
gaterec_kernel(const float* __restrict__ X,  const float* __restrict__ B,
               const float* __restrict__ G1, const float* __restrict__ G2,
               const float* __restrict__ G3, float* __restrict__ Out)
{
    extern __shared__ float smem[];
    float* in_t  = smem;                         // [2][NARR][TILE_F]
    float* out_t = smem + 2 * NARR * TILE_F;     // [TILE_F]

    const int t = threadIdx.x;
    const size_t plane = (size_t)blockIdx.x * (H_DIM * W_DIM);

    const float* srcs[NARR] = { X + plane, B + plane, G1 + plane, G2 + plane, G3 + plane };

    const uint32_t smem_u32 = (uint32_t)__cvta_generic_to_shared(in_t);

    // Coalesced chunk loader (as R2): per array, 4 cp.async16 per thread;
    // each warp instruction covers 8 consecutive rows (8 gmem lines).
    auto load_chunk = [&](int c, int s) {
        const int cb = c * CW;
        #pragma unroll
        for (int a = 0; a < NARR; ++a) {
            const float* src = srcs[a];
            const uint32_t dst_base = smem_u32 + (uint32_t)((s * NARR + a) * TILE_F) * 4u;
            #pragma unroll
            for (int i = 0; i < 4; ++i) {
                int j   = t + H_DIM * i;
                int row = j >> 2;
                int c4  = j & 3;
                cp_async16(dst_base + (uint32_t)(row * RSTRIDE + c4 * 4) * 4u,
                           src + row * W_DIM + cb + c4 * 4);
            }
        }
    };

    load_chunk(0, 0); cp_commit();
    load_chunk(1, 1); cp_commit();

    const bool is_comp = (t < 32);
    const int  lane    = t & 31;
    const int  rbase   = (lane * 4) * RSTRIDE;   // lane owns rows 4*lane .. 4*lane+3

    float cc0 = 0.f, cc1 = 0.f, cc2 = 0.f, cc3 = 0.f;   // carry column (w-1)

    for (int c = 0; c < NCH; ++c) {
        cp_wait<1>();                            // chunk c landed
        __syncthreads();

        if (is_comp) {
            const float* tb = in_t + (c & 1) * NARR * TILE_F;

            #pragma unroll
            for (int g = 0; g < CW / 4; ++g) {   // 4-column groups
                const int o = rbase + g * 4;

                float xv[4][4], bv[4][4], g1v[4][4], g2v[4][4], g3v[4][4];
                #pragma unroll
                for (int k = 0; k < 4; ++k) {
                    float4 v;
                    v = *(const float4*)(tb + 0 * TILE_F + k * RSTRIDE + o);
                    xv[k][0]=v.x;  xv[k][1]=v.y;  xv[k][2]=v.z;  xv[k][3]=v.w;
                    v = *(const float4*)(tb + 1 * TILE_F + k * RSTRIDE + o);
                    bv[k][0]=v.x;  bv[k][1]=v.y;  bv[k][2]=v.z;  bv[k][3]=v.w;
                    v = *(const float4*)(tb + 2 * TILE_F + k * RSTRIDE + o);
                    g1v[k][0]=v.x; g1v[k][1]=v.y; g1v[k][2]=v.z; g1v[k][3]=v.w;
                    v = *(const float4*)(tb + 3 * TILE_F + k * RSTRIDE + o);
                    g2v[k][0]=v.x; g2v[k][1]=v.y; g2v[k][2]=v.z; g2v[k][3]=v.w;
                    v = *(const float4*)(tb + 4 * TILE_F + k * RSTRIDE + o);
                    g3v[k][0]=v.x; g3v[k][1]=v.y; g3v[k][2]=v.z; g3v[k][3]=v.w;
                }

                float ov[4][4];
                #pragma unroll
                for (int i = 0; i < 4; ++i) {
                    // boundary taps across lanes; zero at plane edges
                    float up = __shfl_up_sync(0xffffffffu, cc3, 1);
                    if (lane == 0)  up = 0.f;
                    float dn = __shfl_down_sync(0xffffffffu, cc0, 1);
                    if (lane == 31) dn = 0.f;

                    // put the shfl-dependent FMA last in each chain
                    float n0 = fmaf(g1v[0][i], up,
                               fmaf(g3v[0][i], cc1,
                               fmaf(bv[0][i],  xv[0][i], g2v[0][i] * cc0)));
                    float n1 = fmaf(g1v[1][i], cc0,
                               fmaf(g3v[1][i], cc2,
                               fmaf(bv[1][i],  xv[1][i], g2v[1][i] * cc1)));
                    float n2 = fmaf(g1v[2][i], cc1,
                               fmaf(g3v[2][i], cc3,
                               fmaf(bv[2][i],  xv[2][i], g2v[2][i] * cc2)));
                    float n3 = fmaf(g1v[3][i], cc2,
                               fmaf(g3v[3][i], dn,
                               fmaf(bv[3][i],  xv[3][i], g2v[3][i] * cc3)));

                    cc0 = n0; cc1 = n1; cc2 = n2; cc3 = n3;
                    ov[0][i] = n0; ov[1][i] = n1; ov[2][i] = n2; ov[3][i] = n3;
                }

                #pragma unroll
                for (int k = 0; k < 4; ++k) {
                    float4 v = make_float4(ov[k][0], ov[k][1], ov[k][2], ov[k][3]);
                    *(float4*)(out_t + k * RSTRIDE + o) = v;
                }
            }
        }
        __syncthreads();                         // out_t ready; stage c consumed

        // Cooperative coalesced store of the 128x16 output tile (as R2).
        {
            float* dst = Out + plane + (size_t)c * CW;
            #pragma unroll
            for (int i = 0; i < 4; ++i) {
                int j   = t + H_DIM * i;
                int row = j >> 2;
                int c4  = j & 3;
                float4 v = *(const float4*)(out_t + row * RSTRIDE + c4 * 4);
                *(float4*)(dst + row * W_DIM + c4 * 4) = v;
            }
        }

        if (c + 2 < NCH) load_chunk(c + 2, c & 1);
        cp_commit();
    }
}

extern "C" void kernel_launch(void* const* d_in, const int* in_sizes, int n_in,
                              void* d_out, int out_size) {
    const float* X  = (const float*)d_in[0];
    const float* B  = (const float*)d_in[1];
    const float* G1 = (const float*)d_in[2];
    const float* G2 = (const float*)d_in[3];
    const float* G3 = (const float*)d_in[4];
    float* Out = (float*)d_out;

    const int planes = in_sizes[0] / (H_DIM * W_DIM);       // N*C = 768
    const int dyn_smem = (2 * NARR * TILE_F + TILE_F) * 4;  // 112,640 B

    cudaFuncSetAttribute(gaterec_kernel,
                         cudaFuncAttributeMaxDynamicSharedMemorySize, dyn_smem);

    gaterec_kernel<<<planes, H_DIM, dyn_smem>>>(X, B, G1, G2, G3, Out);
}

// round 4
// speedup vs baseline: 1.6080x; 1.6080x over previous
#include <cuda_runtime.h>
#include <cstdint>

// GateRecurrent2dnoind: H[:,:,h,w] = B*X + G1*H[h-1,w-1] + G2*H[h,w-1] + G3*H[h+1,w-1]
// (8, 96, 128, 128) -> 768 independent (128 x 128) planes, serial scan over W.
//
// R4: register-carry recurrence (proven in R3) with fixed topology:
//   - block = 64 threads, ONE plane. Warp 0 computes: lane L owns rows
//     4L..4L+3 in registers; vertical taps = 2 shfls/step, no per-step barrier.
//   - 2 block barriers per 16-col chunk (16 per plane, vs 128 in R2).
//   - both warps cooperatively load (cp.async, 8-rows-per-warp-instr mapping,
//     full 64B/row sectors) and store via a staged out tile.
//   - smem: packed rows (16 floats) + XOR swizzle c4^=((row>>2)&3):
//     2-way-max conflicts on compute fills, 90KB total -> 2 blocks/SM.
//   - 2-deep cp.async chunk pipeline.

#define H_DIM   128
#define W_DIM   128
#define CW      16                      // chunk width (columns)
#define NCH     (W_DIM / CW)            // 8
#define TILE_Q  (H_DIM * (CW / 4))      // 512 float4 per array tile
#define NARR    5
#define NTHR    64

__device__ __forceinline__ void cp_async16(uint32_t dst, const float* src) {
    asm volatile("cp.async.cg.shared.global [%0], [%1], 16;\n" :: "r"(dst), "l"(src));
}
__device__ __forceinline__ void cp_commit() {
    asm volatile("cp.async.commit_group;\n" ::: "memory");
}
template <int N>
__device__ __forceinline__ void cp_wait() {
    asm volatile("cp.async.wait_group %0;\n" :: "n"(N) : "memory");
}

// 16B-granule index of (row, c4) with bank-decorrelating swizzle.
__device__ __forceinline__ int sw_idx(int row, int c4) {
    return row * 4 + (c4 ^ ((row >> 2) & 3));
}

__global__ void __launch_bounds__(NTHR)
gaterec_kernel(const float* __restrict__ X,  const float* __restrict__ B,
               const float* __restrict__ G1, const float* __restrict__ G2,
               const float* __restrict__ G3, float* __restrict__ Out)
{
    extern __shared__ float4 smem4[];
    float4* in4  = smem4;                       // [2][NARR][TILE_Q]
    float4* out4 = smem4 + 2 * NARR * TILE_Q;   // [TILE_Q]

    const int t = threadIdx.x;
    const size_t plane = (size_t)blockIdx.x * (H_DIM * W_DIM);

    const float* srcs[NARR] = { X + plane, B + plane, G1 + plane, G2 + plane, G3 + plane };

    const uint32_t smem_u32 = (uint32_t)__cvta_generic_to_shared(in4);

    // Cooperative loader: per array 8 cp.async16 per thread; each warp
    // instruction covers 8 consecutive rows x 4 col-quarters (8 gmem lines,
    // 64 contiguous bytes per row -> full sectors).
    auto load_chunk = [&](int c, int s) {
        const int cb = c * CW;
        #pragma unroll
        for (int a = 0; a < NARR; ++a) {
            const float* src = srcs[a];
            const uint32_t base = smem_u32 + (uint32_t)((s * NARR + a) * TILE_Q) * 16u;
            #pragma unroll
            for (int i = 0; i < 8; ++i) {
                int j   = t + NTHR * i;
                int row = j >> 2;
                int c4  = j & 3;
                cp_async16(base + (uint32_t)sw_idx(row, c4) * 16u,
                           src + row * W_DIM + cb + c4 * 4);
            }
        }
    };

    load_chunk(0, 0); cp_commit();
    load_chunk(1, 1); cp_commit();

    const int lane = t & 31;
    const int swz  = lane & 3;                  // (row>>2)&3 for rows 4L..4L+3

    float cc0 = 0.f, cc1 = 0.f, cc2 = 0.f, cc3 = 0.f;   // carry column H[:, w-1]

    for (int c = 0; c < NCH; ++c) {
        cp_wait<1>();
        __syncthreads();                        // chunk c visible to everyone

        if (t < 32) {                           // warp 0: serial recurrence
            const float4* tb = in4 + (c & 1) * NARR * TILE_Q;

            #pragma unroll
            for (int g = 0; g < CW / 4; ++g) {  // 4-column groups
                const int gs = g ^ swz;

                float xv[4][4], bv[4][4], g1v[4][4], g2v[4][4], g3v[4][4];
                #pragma unroll
                for (int k = 0; k < 4; ++k) {
                    const int idx = (4 * lane + k) * 4 + gs;
                    float4 v;
                    v = tb[0 * TILE_Q + idx];
                    xv[k][0]=v.x;  xv[k][1]=v.y;  xv[k][2]=v.z;  xv[k][3]=v.w;
                    v = tb[1 * TILE_Q + idx];
                    bv[k][0]=v.x;  bv[k][1]=v.y;  bv[k][2]=v.z;  bv[k][3]=v.w;
                    v = tb[2 * TILE_Q + idx];
                    g1v[k][0]=v.x; g1v[k][1]=v.y; g1v[k][2]=v.z; g1v[k][3]=v.w;
                    v = tb[3 * TILE_Q + idx];
                    g2v[k][0]=v.x; g2v[k][1]=v.y; g2v[k][2]=v.z; g2v[k][3]=v.w;
                    v = tb[4 * TILE_Q + idx];
                    g3v[k][0]=v.x; g3v[k][1]=v.y; g3v[k][2]=v.z; g3v[k][3]=v.w;
                }

                float ov[4][4];
                #pragma unroll
                for (int i = 0; i < 4; ++i) {
                    float up = __shfl_up_sync(0xffffffffu, cc3, 1);
                    if (lane == 0)  up = 0.f;
                    float dn = __shfl_down_sync(0xffffffffu, cc0, 1);
                    if (lane == 31) dn = 0.f;

                    float n0 = fmaf(g1v[0][i], up,
                               fmaf(g3v[0][i], cc1,
                               fmaf(bv[0][i],  xv[0][i], g2v[0][i] * cc0)));
                    float n1 = fmaf(g1v[1][i], cc0,
                               fmaf(g3v[1][i], cc2,
                               fmaf(bv[1][i],  xv[1][i], g2v[1][i] * cc1)));
                    float n2 = fmaf(g1v[2][i], cc1,
                               fmaf(g3v[2][i], cc3,
                               fmaf(bv[2][i],  xv[2][i], g2v[2][i] * cc2)));
                    float n3 = fmaf(g1v[3][i], cc2,
                               fmaf(g3v[3][i], dn,
                               fmaf(bv[3][i],  xv[3][i], g2v[3][i] * cc3)));

                    cc0 = n0; cc1 = n1; cc2 = n2; cc3 = n3;
                    ov[0][i] = n0; ov[1][i] = n1; ov[2][i] = n2; ov[3][i] = n3;
                }

                #pragma unroll
                for (int k = 0; k < 4; ++k) {
                    out4[(4 * lane + k) * 4 + gs] =
                        make_float4(ov[k][0], ov[k][1], ov[k][2], ov[k][3]);
                }
            }
        }
        __syncthreads();                        // out tile ready; stage consumed

        // Cooperative coalesced store (same 8-rows/instr mapping).
        {
            float* dst = Out + plane + (size_t)c * CW;
            #pragma unroll
            for (int i = 0; i < 8; ++i) {
                int j   = t + NTHR * i;
                int row = j >> 2;
                int c4  = j & 3;
                float4 v = out4[sw_idx(row, c4)];
                *(float4*)(dst + row * W_DIM + c4 * 4) = v;
            }
        }

        if (c + 2 < NCH) load_chunk(c + 2, c & 1);
        cp_commit();
    }
}

extern "C" void kernel_launch(void* const* d_in, const int* in_sizes, int n_in,
                              void* d_out, int out_size) {
    const float* X  = (const float*)d_in[0];
    const float* B  = (const float*)d_in[1];
    const float* G1 = (const float*)d_in[2];
    const float* G2 = (const float*)d_in[3];
    const float* G3 = (const float*)d_in[4];
    float* Out = (float*)d_out;

    const int planes = in_sizes[0] / (H_DIM * W_DIM);        // N*C = 768
    const int dyn_smem = (2 * NARR * TILE_Q + TILE_Q) * 16;  // 90,112 B

    cudaFuncSetAttribute(gaterec_kernel,
                         cudaFuncAttributeMaxDynamicSharedMemorySize, dyn_smem);

    gaterec_kernel<<<planes, NTHR, dyn_smem>>>(X, B, G1, G2, G3, Out);
}